// round 1
// baseline (speedup 1.0000x reference)
#include <cuda_runtime.h>

// Problem constants (fixed by setup_inputs)
constexpr int NN = 10000;     // nodes
constexpr int NE = 160000;    // edges
constexpr int BN = 64;        // columns per block tile
constexpr int BK = 16;        // K chunk
constexpr float HSTEP = 0.1f;

// Scratch (device globals — no allocation allowed)
__device__ float g_xn[NN * 128];          // node features, node-major [n][c]
__device__ float g_xe[(size_t)NE * 128];  // edge features, edge-major [e][c]
__device__ float g_flux[(size_t)NE * 128];
__device__ int   g_rowptr[NN + 1];
__device__ int   g_cursor[NN];
__device__ int   g_elist[2 * NE];         // val = 2*e + side (0 = i-end, 1 = j-end)

// ---------------- CSR build ----------------
__global__ void k_zero_cursor() {
    int i = blockIdx.x * blockDim.x + threadIdx.x;
    if (i < NN) g_cursor[i] = 0;
}
__global__ void k_deg(const int* __restrict__ iInd, const int* __restrict__ jInd) {
    int e = blockIdx.x * blockDim.x + threadIdx.x;
    if (e < NE) {
        atomicAdd(&g_cursor[iInd[e]], 1);
        atomicAdd(&g_cursor[jInd[e]], 1);
    }
}
__global__ void k_scan() {
    __shared__ int part[1024];
    const int t = threadIdx.x;
    constexpr int CH = (NN + 1023) / 1024;  // 10
    int base = t * CH;
    int loc[CH];
    int s = 0;
    #pragma unroll
    for (int k = 0; k < CH; k++) {
        int idx = base + k;
        int v = (idx < NN) ? g_cursor[idx] : 0;
        loc[k] = s;
        s += v;
    }
    part[t] = s;
    __syncthreads();
    for (int off = 1; off < 1024; off <<= 1) {
        int v = 0;
        if (t >= off) v = part[t - off];
        __syncthreads();
        if (t >= off) part[t] += v;
        __syncthreads();
    }
    int pre = (t == 0) ? 0 : part[t - 1];
    #pragma unroll
    for (int k = 0; k < CH; k++) {
        int idx = base + k;
        if (idx < NN) {
            int rp = pre + loc[k];
            g_rowptr[idx] = rp;
            g_cursor[idx] = rp;
        }
    }
    if (t == 1023) g_rowptr[NN] = part[1023];
}
__global__ void k_fill(const int* __restrict__ iInd, const int* __restrict__ jInd) {
    int e = blockIdx.x * blockDim.x + threadIdx.x;
    if (e < NE) {
        int p = atomicAdd(&g_cursor[iInd[e]], 1);
        g_elist[p] = 2 * e;
        int q = atomicAdd(&g_cursor[jInd[e]], 1);
        g_elist[q] = 2 * e + 1;
    }
}

// ---------------- SGEMM core: acc[M x 64-tile] += A[M x KD] * Bs[KD x 64] ----------------
template <int M, int KD>
__device__ __forceinline__ void gemm_acc(const float* __restrict__ A,
                                         const float* __restrict__ Bs,
                                         float* __restrict__ As,
                                         int t, float acc[][4]) {
    const int tm = t >> 4, tn = t & 15;
    constexpr int TM = M / 16;
    for (int k0 = 0; k0 < KD; k0 += BK) {
        // Load A chunk [M][BK] transposed into As[BK][M]
        #pragma unroll
        for (int p = 0; p < M / 64; p++) {
            int m = p * 64 + (t >> 2);
            int kq = (t & 3) * 4;
            float4 v = *reinterpret_cast<const float4*>(A + (size_t)m * KD + k0 + kq);
            As[(kq + 0) * M + m] = v.x;
            As[(kq + 1) * M + m] = v.y;
            As[(kq + 2) * M + m] = v.z;
            As[(kq + 3) * M + m] = v.w;
        }
        __syncthreads();
        #pragma unroll
        for (int kk = 0; kk < BK; kk++) {
            float a[TM];
            #pragma unroll
            for (int r = 0; r < TM; r++) a[r] = As[kk * M + tm * TM + r];
            float4 b = *reinterpret_cast<const float4*>(Bs + (k0 + kk) * BN + tn * 4);
            #pragma unroll
            for (int r = 0; r < TM; r++) {
                acc[r][0] = fmaf(a[r], b.x, acc[r][0]);
                acc[r][1] = fmaf(a[r], b.y, acc[r][1]);
                acc[r][2] = fmaf(a[r], b.z, acc[r][2]);
                acc[r][3] = fmaf(a[r], b.w, acc[r][3]);
            }
        }
        __syncthreads();
    }
}

// MODE: 0 = open -> g_xn, 4 = open -> g_xe, 1 = edge layer, 2 = node layer, 3 = close
template <int M, int KD, int MODE>
__global__ void __launch_bounds__(256)
dl_kernel(const float* __restrict__ A1, const float* __restrict__ A2,
          const float* __restrict__ src, float* __restrict__ dst,
          const int* __restrict__ iInd, const int* __restrict__ jInd, int ncols) {
    extern __shared__ float sm[];
    float* Xs = sm;                                   // KD x BN
    float* Ts = sm + KD * BN;                         // 128 x BN (modes 0,1,2,4)
    float* As = (MODE == 3) ? Ts : (Ts + 128 * BN);   // BK x M
    int*   sI = (int*)(As + BK * M);                  // 2*BN ints (mode 1)

    const int t = threadIdx.x;
    const int n0 = blockIdx.x * BN;

    // ---- Build X tile ----
    if (MODE == 0 || MODE == 4) {
        int nl = t & 63;
        int r0 = t >> 6;
        int n = n0 + nl;
        bool valid = n < ncols;
        for (int r = r0; r < KD; r += 4)
            Xs[r * BN + nl] = valid ? src[(size_t)r * ncols + n] : 0.f;
    } else if (MODE == 1) {
        int ep = t >> 2, cg = t & 3;
        int e = n0 + ep;  // grid exactly covers NE
        int i = iInd[e], j = jInd[e];
        if (cg == 0) { sI[ep] = i; sI[BN + ep] = j; }
        const float4* xi4 = reinterpret_cast<const float4*>(g_xn + (size_t)i * 128 + cg * 32);
        const float4* xj4 = reinterpret_cast<const float4*>(g_xn + (size_t)j * 128 + cg * 32);
        const float4* xe4 = reinterpret_cast<const float4*>(g_xe + (size_t)e * 128 + cg * 32);
        #pragma unroll
        for (int u = 0; u < 8; u++) {
            float4 vi = xi4[u], vj = xj4[u], ve = xe4[u];
            int c = cg * 32 + u * 4;
            Xs[(c + 0) * BN + ep] = 0.5f * (vi.x + vj.x);
            Xs[(c + 1) * BN + ep] = 0.5f * (vi.y + vj.y);
            Xs[(c + 2) * BN + ep] = 0.5f * (vi.z + vj.z);
            Xs[(c + 3) * BN + ep] = 0.5f * (vi.w + vj.w);
            Xs[(128 + c + 0) * BN + ep] = ve.x;
            Xs[(128 + c + 1) * BN + ep] = ve.y;
            Xs[(128 + c + 2) * BN + ep] = ve.z;
            Xs[(128 + c + 3) * BN + ep] = ve.w;
            Xs[(256 + c + 0) * BN + ep] = vi.x - vj.x;
            Xs[(256 + c + 1) * BN + ep] = vi.y - vj.y;
            Xs[(256 + c + 2) * BN + ep] = vi.z - vj.z;
            Xs[(256 + c + 3) * BN + ep] = vi.w - vj.w;
        }
    } else if (MODE == 2) {
        int ep = t >> 2, cg = t & 3, c0 = cg * 32;
        int n = n0 + ep;
        bool valid = n < NN;
        float4 s[8], d[8];
        #pragma unroll
        for (int u = 0; u < 8; u++) {
            s[u] = make_float4(0.f, 0.f, 0.f, 0.f);
            d[u] = make_float4(0.f, 0.f, 0.f, 0.f);
        }
        if (valid) {
            int beg = g_rowptr[n], end = g_rowptr[n + 1];
            for (int p = beg; p < end; p++) {
                int v = g_elist[p];
                int e = v >> 1;
                float sg = (v & 1) ? -1.f : 1.f;
                const float4* f4 = reinterpret_cast<const float4*>(g_flux + (size_t)e * 128 + c0);
                #pragma unroll
                for (int u = 0; u < 8; u++) {
                    float4 f = f4[u];
                    s[u].x += f.x; s[u].y += f.y; s[u].z += f.z; s[u].w += f.w;
                    d[u].x = fmaf(sg, f.x, d[u].x);
                    d[u].y = fmaf(sg, f.y, d[u].y);
                    d[u].z = fmaf(sg, f.z, d[u].z);
                    d[u].w = fmaf(sg, f.w, d[u].w);
                }
            }
        }
        const float4* xn4 = reinterpret_cast<const float4*>(g_xn + (size_t)n * 128 + c0);
        #pragma unroll
        for (int u = 0; u < 8; u++) {
            float4 xv = valid ? xn4[u] : make_float4(0.f, 0.f, 0.f, 0.f);
            int c = c0 + u * 4;
            Xs[(c + 0) * BN + ep] = 0.5f * s[u].x;   // aveE
            Xs[(c + 1) * BN + ep] = 0.5f * s[u].y;
            Xs[(c + 2) * BN + ep] = 0.5f * s[u].z;
            Xs[(c + 3) * BN + ep] = 0.5f * s[u].w;
            Xs[(128 + c + 0) * BN + ep] = d[u].x;    // divE
            Xs[(128 + c + 1) * BN + ep] = d[u].y;
            Xs[(128 + c + 2) * BN + ep] = d[u].z;
            Xs[(128 + c + 3) * BN + ep] = d[u].w;
            Xs[(256 + c + 0) * BN + ep] = xv.x;      // xn
            Xs[(256 + c + 1) * BN + ep] = xv.y;
            Xs[(256 + c + 2) * BN + ep] = xv.z;
            Xs[(256 + c + 3) * BN + ep] = xv.w;
        }
    } else {  // MODE 3: close, X = g_xn (node-major)
        int ep = t >> 2, cg = t & 3, c0 = cg * 32;
        int n = n0 + ep;
        bool valid = n < ncols;
        const float4* xn4 = reinterpret_cast<const float4*>(g_xn + (size_t)n * 128 + c0);
        #pragma unroll
        for (int u = 0; u < 8; u++) {
            float4 xv = valid ? xn4[u] : make_float4(0.f, 0.f, 0.f, 0.f);
            int c = c0 + u * 4;
            Xs[(c + 0) * BN + ep] = xv.x;
            Xs[(c + 1) * BN + ep] = xv.y;
            Xs[(c + 2) * BN + ep] = xv.z;
            Xs[(c + 3) * BN + ep] = xv.w;
        }
    }
    __syncthreads();

    constexpr int TM = M / 16;
    const int tm = t >> 4, tn = t & 15;
    float acc[TM][4];
    #pragma unroll
    for (int r = 0; r < TM; r++) {
        acc[r][0] = 0.f; acc[r][1] = 0.f; acc[r][2] = 0.f; acc[r][3] = 0.f;
    }

    gemm_acc<M, KD>(A1, Xs, As, t, acc);

    if (MODE == 3) {
        // Single GEMM, write channel-major to d_out (xn region)
        #pragma unroll
        for (int q = 0; q < 4; q++) {
            int n = n0 + tn * 4 + q;
            if (n < ncols) {
                #pragma unroll
                for (int r = 0; r < TM; r++)
                    dst[(size_t)(tm * TM + r) * ncols + n] = acc[r][q];
            }
        }
        return;
    }

    // tanh -> Ts
    #pragma unroll
    for (int r = 0; r < TM; r++)
        #pragma unroll
        for (int q = 0; q < 4; q++)
            Ts[(tm * TM + r) * BN + tn * 4 + q] = tanhf(acc[r][q]);

    #pragma unroll
    for (int r = 0; r < TM; r++) {
        acc[r][0] = 0.f; acc[r][1] = 0.f; acc[r][2] = 0.f; acc[r][3] = 0.f;
    }

    gemm_acc<M, 128>(A2, Ts, As, t, acc);

    if (MODE == 0) {
        #pragma unroll
        for (int q = 0; q < 4; q++) {
            int n = n0 + tn * 4 + q;
            if (n < ncols) {
                float* dp = g_xn + (size_t)n * 128 + tm * TM;
                #pragma unroll
                for (int r = 0; r < TM; r++) dp[r] = acc[r][q];
            }
        }
    } else if (MODE == 4) {
        #pragma unroll
        for (int q = 0; q < 4; q++) {
            int n = n0 + tn * 4 + q;
            if (n < ncols) {
                float* dp = g_xe + (size_t)n * 128 + tm * TM;
                #pragma unroll
                for (int r = 0; r < TM; r++) dp[r] = acc[r][q];
            }
        }
    } else if (MODE == 1) {
        // flux out + xe -= H*flux (xe_old still in Xs rows 128..255)
        #pragma unroll
        for (int q = 0; q < 4; q++) {
            int nl = tn * 4 + q;
            int e = n0 + nl;
            float* xp = g_xe + (size_t)e * 128 + tm * TM;
            float* fp = g_flux + (size_t)e * 128 + tm * TM;
            #pragma unroll
            for (int r = 0; r < TM; r++) {
                float f = acc[r][q];
                fp[r] = f;
                xp[r] = Xs[(128 + tm * TM + r) * BN + nl] - HSTEP * f;
            }
        }
    } else {  // MODE 2: xn -= H*dxn (xn_old in Xs rows 256..383)
        #pragma unroll
        for (int q = 0; q < 4; q++) {
            int nl = tn * 4 + q;
            int n = n0 + nl;
            if (n < NN) {
                float* xp = g_xn + (size_t)n * 128 + tm * TM;
                #pragma unroll
                for (int r = 0; r < TM; r++)
                    xp[r] = Xs[(256 + tm * TM + r) * BN + nl] - HSTEP * acc[r][q];
            }
        }
    }
}

// Final: g_xe [e][c] -> out [c][e]
__global__ void k_transpose(float* __restrict__ out) {
    __shared__ float tile[32][33];
    int e0 = blockIdx.x * 32, c0 = blockIdx.y * 32;
    int tx = threadIdx.x, ty = threadIdx.y;
    tile[ty][tx] = g_xe[(size_t)(e0 + ty) * 128 + c0 + tx];
    __syncthreads();
    out[(size_t)(c0 + ty) * NE + (e0 + tx)] = tile[tx][ty];
}

extern "C" void kernel_launch(void* const* d_in, const int* in_sizes, int n_in,
                              void* d_out, int out_size) {
    const float* xn_in = (const float*)d_in[0];
    const float* xe_in = (const float*)d_in[1];
    const int*   iInd  = (const int*)d_in[2];
    const int*   jInd  = (const int*)d_in[3];
    int wi = (n_in >= 14) ? 5 : 4;  // skip 'nnodes' scalar if present
    const float* K1Nopen = (const float*)d_in[wi + 0];
    const float* K2Nopen = (const float*)d_in[wi + 1];
    const float* K1Eopen = (const float*)d_in[wi + 2];
    const float* K2Eopen = (const float*)d_in[wi + 3];
    const float* KNclose = (const float*)d_in[wi + 4];
    const float* KE1     = (const float*)d_in[wi + 5];
    const float* KE2     = (const float*)d_in[wi + 6];
    const float* KN1     = (const float*)d_in[wi + 7];
    const float* KN2     = (const float*)d_in[wi + 8];
    float* out = (float*)d_out;

    const int smOpen  = (64 + 128) * BN * 4 + BK * 128 * 4;              // 57344
    const int smEdge  = (384 + 128) * BN * 4 + BK * 128 * 4 + 2 * BN * 4; // 139776
    const int smNode  = (384 + 128) * BN * 4 + BK * 128 * 4;             // 139264
    const int smClose = 128 * BN * 4 + BK * 64 * 4;                      // 36864

    cudaFuncSetAttribute(dl_kernel<128, 64, 0>,  cudaFuncAttributeMaxDynamicSharedMemorySize, smOpen);
    cudaFuncSetAttribute(dl_kernel<128, 64, 4>,  cudaFuncAttributeMaxDynamicSharedMemorySize, smOpen);
    cudaFuncSetAttribute(dl_kernel<128, 384, 1>, cudaFuncAttributeMaxDynamicSharedMemorySize, smEdge);
    cudaFuncSetAttribute(dl_kernel<128, 384, 2>, cudaFuncAttributeMaxDynamicSharedMemorySize, smNode);

    const int gN = (NN + BN - 1) / BN;  // 157
    const int gE = NE / BN;             // 2500

    // CSR build (same result every call; all capturable)
    k_zero_cursor<<<(NN + 255) / 256, 256>>>();
    k_deg<<<(NE + 255) / 256, 256>>>(iInd, jInd);
    k_scan<<<1, 1024>>>();
    k_fill<<<(NE + 255) / 256, 256>>>(iInd, jInd);

    // Opening double layers
    dl_kernel<128, 64, 0><<<gN, 256, smOpen>>>(K1Nopen, K2Nopen, xn_in, nullptr, nullptr, nullptr, NN);
    dl_kernel<128, 64, 4><<<gE, 256, smOpen>>>(K1Eopen, K2Eopen, xe_in, nullptr, nullptr, nullptr, NE);

    // 4 PDE layers
    for (int l = 0; l < 4; l++) {
        dl_kernel<128, 384, 1><<<gE, 256, smEdge>>>(
            KE1 + (size_t)l * 128 * 384, KE2 + (size_t)l * 128 * 128,
            nullptr, nullptr, iInd, jInd, NE);
        dl_kernel<128, 384, 2><<<gN, 256, smNode>>>(
            KN1 + (size_t)l * 128 * 384, KN2 + (size_t)l * 128 * 128,
            nullptr, nullptr, nullptr, nullptr, NN);
    }

    // Close + output assembly
    dl_kernel<64, 128, 3><<<gN, 256, smClose>>>(KNclose, nullptr, nullptr, out, nullptr, nullptr, NN);
    dim3 tb(32, 32), tg(NE / 32, 128 / 32);
    k_transpose<<<tg, tb>>>(out + (size_t)64 * NN);
}